// round 1
// baseline (speedup 1.0000x reference)
#include <cuda_runtime.h>
#include <cuda_bf16.h>

// Problem shapes (fixed by reference setup_inputs)
#define B    4
#define CIN  512
#define OUT  256
#define NN   4096

// Scratch (no cudaMalloc allowed)
__device__ float g_X[B * CIN];   // X[b,c] = sum_n x[b,c,n]
__device__ float g_E[B * OUT];   // E[b,o] = elu(sum_c W1[o,c]*X[b,c])

// ---------------------------------------------------------------------------
// Kernel 1: reduce x over the N dimension. One block per (b,c) row.
// x layout: [B, CIN, 1, NN] contiguous -> row base (b*CIN+c)*NN
// ---------------------------------------------------------------------------
__global__ __launch_bounds__(256) void k_rowsum(const float* __restrict__ x) {
    const int row = blockIdx.x;                 // 0 .. B*CIN-1
    const float4* p = reinterpret_cast<const float4*>(x + (size_t)row * NN);
    float s = 0.f;
    // NN/4 = 1024 float4 per row, 256 threads -> 4 iters each
    #pragma unroll
    for (int i = threadIdx.x; i < NN / 4; i += 256) {
        float4 v = p[i];
        s += (v.x + v.y) + (v.z + v.w);
    }
    // warp reduce
    #pragma unroll
    for (int off = 16; off > 0; off >>= 1)
        s += __shfl_down_sync(0xffffffffu, s, off);
    __shared__ float sm[8];
    if ((threadIdx.x & 31) == 0) sm[threadIdx.x >> 5] = s;
    __syncthreads();
    if (threadIdx.x < 8) {
        float t = sm[threadIdx.x];
        #pragma unroll
        for (int off = 4; off > 0; off >>= 1)
            t += __shfl_down_sync(0xffu, t, off);
        if (threadIdx.x == 0) g_X[row] = t;
    }
}

// ---------------------------------------------------------------------------
// Kernel 2: E[b,o] = elu( sum_c W1[o,c] * X[b,c] ).  One block per (b,o).
// ---------------------------------------------------------------------------
__global__ __launch_bounds__(128) void k_dot_elu(const float* __restrict__ W1) {
    const int bo = blockIdx.x;      // 0 .. B*OUT-1
    const int b  = bo >> 8;         // OUT = 256
    const int o  = bo & 255;
    const float* w = W1 + (size_t)o * CIN;
    const float* xv = g_X + (size_t)b * CIN;
    float s = 0.f;
    #pragma unroll
    for (int c = threadIdx.x; c < CIN; c += 128)
        s = fmaf(w[c], xv[c], s);
    #pragma unroll
    for (int off = 16; off > 0; off >>= 1)
        s += __shfl_down_sync(0xffffffffu, s, off);
    __shared__ float sm[4];
    if ((threadIdx.x & 31) == 0) sm[threadIdx.x >> 5] = s;
    __syncthreads();
    if (threadIdx.x == 0) {
        float t = sm[0] + sm[1] + sm[2] + sm[3];
        g_E[bo] = (t > 0.f) ? t : expm1f(t);   // elu, alpha=1
    }
}

// ---------------------------------------------------------------------------
// Kernel 3: broadcast E[b,o] across the N dimension of the output.
// out layout: [B, OUT, 1, NN] -> out[(b*OUT+o)*NN + n] = E[b,o]
// 1M float4 stores, one per thread.
// ---------------------------------------------------------------------------
__global__ __launch_bounds__(256) void k_broadcast(float* __restrict__ out) {
    const int i  = blockIdx.x * 256 + threadIdx.x;   // float4 index
    const int bo = i >> 10;                          // NN/4 = 1024 float4 per row
    const float v = g_E[bo];
    reinterpret_cast<float4*>(out)[i] = make_float4(v, v, v, v);
}

extern "C" void kernel_launch(void* const* d_in, const int* in_sizes, int n_in,
                              void* d_out, int out_size) {
    const float* x  = (const float*)d_in[0];   // [B, CIN, 1, NN]
    const float* W1 = (const float*)d_in[1];   // [OUT, CIN]
    // d_in[2] = w2, d_in[3] = bias_mat: provably unused (softmax over size-1 axis == 1)
    float* out = (float*)d_out;                // [B, OUT, 1, NN]

    k_rowsum<<<B * CIN, 256>>>(x);
    k_dot_elu<<<B * OUT, 128>>>(W1);
    k_broadcast<<<(B * OUT * NN / 4) / 256, 256>>>(out);
}

// round 2
// speedup vs baseline: 1.2179x; 1.2179x over previous
#include <cuda_runtime.h>
#include <cuda_bf16.h>

// Problem shapes (fixed by reference setup_inputs)
#define B    4
#define CIN  512
#define OUT  256
#define NN   4096

// Scratch (no cudaMalloc allowed)
__device__ float g_X[B * CIN];   // X[b,c] = sum_n x[b,c,n]

// ---------------------------------------------------------------------------
// Kernel 1: reduce x over N. One block per (b,c) row (16 KB each).
// 256 threads x 4 float4, loads FRONT-BATCHED for MLP=4 per thread.
// ---------------------------------------------------------------------------
__global__ __launch_bounds__(256) void k_rowsum(const float* __restrict__ x) {
    const int row = blockIdx.x;                 // 0 .. B*CIN-1
    const float4* __restrict__ p =
        reinterpret_cast<const float4*>(x + (size_t)row * NN);
    const int t = threadIdx.x;

    // Issue all 4 independent 128-bit loads before ANY arithmetic.
    float4 v0 = p[t];
    float4 v1 = p[t + 256];
    float4 v2 = p[t + 512];
    float4 v3 = p[t + 768];

    float s0 = (v0.x + v0.y) + (v0.z + v0.w);
    float s1 = (v1.x + v1.y) + (v1.z + v1.w);
    float s2 = (v2.x + v2.y) + (v2.z + v2.w);
    float s3 = (v3.x + v3.y) + (v3.z + v3.w);
    float s  = (s0 + s1) + (s2 + s3);

    #pragma unroll
    for (int off = 16; off > 0; off >>= 1)
        s += __shfl_down_sync(0xffffffffu, s, off);

    __shared__ float sm[8];
    if ((t & 31) == 0) sm[t >> 5] = s;
    __syncthreads();
    if (t < 8) {
        float u = sm[t];
        #pragma unroll
        for (int off = 4; off > 0; off >>= 1)
            u += __shfl_down_sync(0xffu, u, off);
        if (t == 0) g_X[row] = u;
    }
}

// ---------------------------------------------------------------------------
// Kernel 2 (fused dot + elu + broadcast): one block per output row (b,o).
// Compute E = elu( dot(W1[o,:], X[b,:]) ), then stream 16 KB of E.
// ---------------------------------------------------------------------------
__global__ __launch_bounds__(256) void k_out(const float* __restrict__ W1,
                                             float* __restrict__ out) {
    const int bo = blockIdx.x;      // 0 .. B*OUT-1
    const int b  = bo >> 8;         // OUT = 256
    const int o  = bo & 255;
    const int t  = threadIdx.x;

    // dot over CIN=512: each thread handles c = t and c = t+256
    const float* __restrict__ w  = W1 + (size_t)o * CIN;
    const float* __restrict__ xv = g_X + (size_t)b * CIN;
    float s = fmaf(w[t], xv[t], w[t + 256] * xv[t + 256]);

    #pragma unroll
    for (int off = 16; off > 0; off >>= 1)
        s += __shfl_down_sync(0xffffffffu, s, off);

    __shared__ float sm[8];
    __shared__ float e_val;
    if ((t & 31) == 0) sm[t >> 5] = s;
    __syncthreads();
    if (t == 0) {
        float u = ((sm[0] + sm[1]) + (sm[2] + sm[3]))
                + ((sm[4] + sm[5]) + (sm[6] + sm[7]));
        e_val = (u > 0.f) ? u : expm1f(u);     // elu, alpha=1
    }
    __syncthreads();

    const float  v  = e_val;
    const float4 v4 = make_float4(v, v, v, v);
    float4* __restrict__ q =
        reinterpret_cast<float4*>(out + (size_t)bo * NN);
    // 1024 float4 per row, 256 threads -> 4 stores each
    q[t]       = v4;
    q[t + 256] = v4;
    q[t + 512] = v4;
    q[t + 768] = v4;
}

extern "C" void kernel_launch(void* const* d_in, const int* in_sizes, int n_in,
                              void* d_out, int out_size) {
    const float* x  = (const float*)d_in[0];   // [B, CIN, 1, NN]
    const float* W1 = (const float*)d_in[1];   // [OUT, CIN]
    // d_in[2] = w2, d_in[3] = bias_mat: unused (softmax over size-1 axis == 1)
    float* out = (float*)d_out;                // [B, OUT, 1, NN]

    k_rowsum<<<B * CIN, 256>>>(x);
    k_out<<<B * OUT, 256>>>(W1, out);
}